// round 12
// baseline (speedup 1.0000x reference)
#include <cuda_runtime.h>
#include <cuda_fp16.h>
#include <cstdint>

#define BATCH 4
#define SEQ   4096
#define EMB   1024
#define HEAD  64
#define H3    192
#define MTOT  (BATCH*SEQ)   // 16384

// Scratch (allocation-free rule: device globals)
__device__ __align__(16) __half g_x16[MTOT * EMB];    // 33.5 MB fp16 x
__device__ __align__(16) __half g_wq16[EMB * H3];
__device__ __align__(16) __half g_wo16[HEAD * EMB];
__device__ __align__(16) __half g_q16[MTOT * HEAD];   // q pre-scaled
__device__ __align__(16) __half g_k16[MTOT * HEAD];
__device__ __align__(16) __half g_v16[MTOT * HEAD];
__device__ __align__(16) float  g_po[2][MTOT * HEAD]; // partial O (unnormalized)
__device__ __align__(16) float  g_pm[2][MTOT];
__device__ __align__(16) float  g_pl[2][MTOT];

// ---------------------------------------------------------------------------
// Helpers
// ---------------------------------------------------------------------------
__device__ __forceinline__ float exp2a(float x) {
    float y;
    asm("ex2.approx.f32 %0, %1;" : "=f"(y) : "f"(x));
    return y;
}
__device__ __forceinline__ void mma_f16(float c[4], const uint32_t a[4],
                                        uint32_t b0, uint32_t b1) {
    asm volatile(
        "mma.sync.aligned.m16n8k16.row.col.f32.f16.f16.f32 "
        "{%0,%1,%2,%3}, {%4,%5,%6,%7}, {%8,%9}, {%0,%1,%2,%3};\n"
        : "+f"(c[0]), "+f"(c[1]), "+f"(c[2]), "+f"(c[3])
        : "r"(a[0]), "r"(a[1]), "r"(a[2]), "r"(a[3]), "r"(b0), "r"(b1));
}
__device__ __forceinline__ void ldsm_x4(uint32_t r[4], uint32_t addr) {
    asm volatile("ldmatrix.sync.aligned.m8n8.x4.shared.b16 {%0,%1,%2,%3}, [%4];"
                 : "=r"(r[0]), "=r"(r[1]), "=r"(r[2]), "=r"(r[3]) : "r"(addr));
}
__device__ __forceinline__ void ldsm_x4t(uint32_t r[4], uint32_t addr) {
    asm volatile("ldmatrix.sync.aligned.m8n8.x4.trans.shared.b16 {%0,%1,%2,%3}, [%4];"
                 : "=r"(r[0]), "=r"(r[1]), "=r"(r[2]), "=r"(r[3]) : "r"(addr));
}
__device__ __forceinline__ void cp16(uint32_t dst, const void* src) {
    asm volatile("cp.async.cg.shared.global [%0], [%1], 16;" :: "r"(dst), "l"(src));
}
__device__ __forceinline__ uint32_t packh2(float x, float y) {
    __half2 h = __floats2half2_rn(x, y);
    return *reinterpret_cast<uint32_t*>(&h);
}

#define QSCALE (0.125f * 1.44269504088896340736f)   // (1/sqrt(64)) * log2(e)

// ---------------------------------------------------------------------------
// Kernel 0: fp32 -> fp16 prepass for x, W_qkv, W_out. 8 elements per thread.
// ---------------------------------------------------------------------------
#define NX  (MTOT * EMB)    // 16777216
#define NWQ (EMB * H3)      // 196608
#define NWO (HEAD * EMB)    // 65536
#define CONV_BLOCKS ((NX + NWQ + NWO) / (8 * 256))   // 8320

__global__ __launch_bounds__(256) void conv16(const float* __restrict__ x,
                                              const float* __restrict__ Wq,
                                              const float* __restrict__ Wo) {
    size_t i = ((size_t)blockIdx.x * 256 + threadIdx.x) * 8;
    const float* src;
    __half* dst;
    size_t off;
    if (i < NX)            { src = x;  dst = g_x16;  off = i; }
    else if (i < NX + NWQ) { src = Wq; dst = g_wq16; off = i - NX; }
    else                   { src = Wo; dst = g_wo16; off = i - NX - NWQ; }
    float4 a = *reinterpret_cast<const float4*>(src + off);
    float4 b = *reinterpret_cast<const float4*>(src + off + 4);
    uint4 o = make_uint4(packh2(a.x, a.y), packh2(a.z, a.w),
                         packh2(b.x, b.y), packh2(b.z, b.w));
    *reinterpret_cast<uint4*>(dst + off) = o;
}

// ---------------------------------------------------------------------------
// Kernel 1: QKV projection, pure fp16 GEMM, 3-stage cp.async ring
// (attention-proven pattern, 1 sync/tile). Grid (3, M/128): the 3 output
// types (q/k/v) share each x tile through L2.
// ---------------------------------------------------------------------------
#define QSTG 27648                          // stage bytes: A 128*144 + B 64*144
#define QKV_SMEM (3 * QSTG)                 // 82944 B

__global__ __launch_bounds__(256, 2) void qkv_fp16(const float* __restrict__ bias) {
    extern __shared__ __half qsm[];

    const int bn = blockIdx.x * 64;    // 0=q, 64=k, 128=v (fast dim -> L2 share)
    const int bm = blockIdx.y * 128;
    const int tid = threadIdx.x;
    const int w = tid >> 5;
    const int lane = tid & 31;
    const int ly = lane >> 2;
    const int lx = lane & 3;

    const uint32_t smb = (uint32_t)__cvta_generic_to_shared(qsm);

    // fragment offsets within a stage
    const int ar = (lane & 7) + ((lane >> 3) & 1) * 8;
    const uint32_t offA = (w * 16 + ar) * 144 + (lane >> 4) * 16;
    const uint32_t offB = 18432 + (lane & 15) * 144 + (lane >> 4) * 16;

    // cp.async chunk mapping
    const int arow = tid >> 3, acol = tid & 7;          // + i*32 rows (4 iters)
    const int brow = tid >> 3, bcol = tid & 7;          // + i*32 rows (2 iters)

    auto load_tile = [&](int t) {
        const uint32_t sb = smb + (t % 3) * QSTG;
#pragma unroll
        for (int i = 0; i < 4; i++) {
            int row = arow + i * 32;
            cp16(sb + row * 144 + acol * 16,
                 g_x16 + (size_t)(bm + row) * EMB + t * 64 + acol * 8);
        }
#pragma unroll
        for (int i = 0; i < 2; i++) {
            int row = brow + i * 32;
            cp16(sb + 18432 + row * 144 + bcol * 16,
                 g_wq16 + (size_t)(t * 64 + row) * H3 + bn + bcol * 8);
        }
        asm volatile("cp.async.commit_group;");
    };

    load_tile(0);

    float acc[8][4] = {};

    for (int t = 0; t < 16; t++) {
        if (t + 1 < 16) {
            load_tile(t + 1);
            asm volatile("cp.async.wait_group 1;");
        } else {
            asm volatile("cp.async.wait_group 0;");
        }
        __syncthreads();

        const uint32_t sb = smb + (t % 3) * QSTG;
        uint32_t Aa[4][4];
#pragma unroll
        for (int ks = 0; ks < 4; ks++) ldsm_x4(Aa[ks], sb + offA + ks * 32);

#pragma unroll
        for (int ks = 0; ks < 4; ks++) {
#pragma unroll
            for (int p = 0; p < 4; p++) {
                uint32_t bb[4];
                ldsm_x4t(bb, sb + offB + ks * 2304 + p * 32);
                mma_f16(acc[2 * p    ], Aa[ks], bb[0], bb[1]);
                mma_f16(acc[2 * p + 1], Aa[ks], bb[2], bb[3]);
            }
        }
    }

    __half* dst = (blockIdx.x == 0) ? g_q16 : (blockIdx.x == 1) ? g_k16 : g_v16;
    const float sc = (blockIdx.x == 0) ? QSCALE : 1.0f;
    int r0 = bm + w * 16 + ly;
#pragma unroll
    for (int nb = 0; nb < 8; nb++) {
        int col = nb * 8 + 2 * lx;
        float b0 = bias[bn + col], b1 = bias[bn + col + 1];
        __half2 h0 = __floats2half2_rn((acc[nb][0] + b0) * sc, (acc[nb][1] + b1) * sc);
        __half2 h1 = __floats2half2_rn((acc[nb][2] + b0) * sc, (acc[nb][3] + b1) * sc);
        *reinterpret_cast<__half2*>(&dst[(size_t)r0 * HEAD + col]) = h0;
        *reinterpret_cast<__half2*>(&dst[(size_t)(r0 + 8) * HEAD + col]) = h1;
    }
}

// ---------------------------------------------------------------------------
// Kernel 2: fp16 flash attention. 3-stage cp.async ring, register-resident P,
// split-KV (z). Unchanged from R11.
// ---------------------------------------------------------------------------
#define BQ     128
#define KVHALF (SEQ / 2)
#define NTILE  (KVHALF / 64)
#define STG_SZ (2 * 64 * 144)
#define ATT_SMEM (3 * STG_SZ + 128 * 144)

__global__ __launch_bounds__(256, 2) void attn_fp16() {
    extern __shared__ __half smh[];

    const int b    = blockIdx.y;
    const int q0   = blockIdx.x * BQ;
    const int z    = blockIdx.z;
    const int tid  = threadIdx.x;
    const int w    = tid >> 5;
    const int lane = tid & 31;
    const int ly   = lane >> 2;
    const int lx   = lane & 3;

    const uint32_t smb = (uint32_t)__cvta_generic_to_shared(smh);
    const uint32_t bQ  = smb + 3 * STG_SZ;

    const int srow = tid >> 2;
    const int sc   = (tid & 3) * 2;
    const uint32_t dOff = srow * 144 + sc * 16;
    const size_t gb = (size_t)b * SEQ * HEAD;
    const int kv_beg = z * KVHALF;

    {
        const __half* ks = g_k16 + gb + (size_t)(kv_beg + srow) * HEAD + sc * 8;
        const __half* vs = g_v16 + gb + (size_t)(kv_beg + srow) * HEAD + sc * 8;
        cp16(smb + dOff, ks); cp16(smb + dOff + 16, ks + 8);
        cp16(smb + 9216 + dOff, vs); cp16(smb + 9216 + dOff + 16, vs + 8);
        asm volatile("cp.async.commit_group;");
    }

#pragma unroll
    for (int i = 0; i < 4; i++) {
        int idx = tid + i * 256;
        int row = idx >> 3, c = idx & 7;
        uint4 v = *reinterpret_cast<const uint4*>(
            g_q16 + gb + (size_t)(q0 + row) * HEAD + c * 8);
        *reinterpret_cast<uint4*>(
            reinterpret_cast<char*>(smh) + 3 * STG_SZ + row * 144 + c * 16) = v;
    }
    __syncthreads();

    uint32_t Aq[4][4];
    {
        const int qr = (lane & 7) + ((lane >> 3) & 1) * 8;
        uint32_t aQ = bQ + (w * 16 + qr) * 144 + (lane >> 4) * 16;
#pragma unroll
        for (int ks = 0; ks < 4; ks++) ldsm_x4(Aq[ks], aQ + ks * 32);
    }

    float O[8][4];
    float mrow0 = -1e30f, mrow1 = -1e30f, lrow0 = 0.f, lrow1 = 0.f;
#pragma unroll
    for (int nb = 0; nb < 8; nb++)
#pragma unroll
        for (int j = 0; j < 4; j++) O[nb][j] = 0.f;

    const uint32_t kOff = (((lane >> 4) & 1) * 8 + (lane & 7)) * 144 + ((lane >> 3) & 1) * 16;
    const uint32_t vOff = 9216 + (lane & 15) * 144 + (lane >> 4) * 16;

    for (int t = 0; t < NTILE; t++) {
        const uint32_t stb = smb + (t % 3) * STG_SZ;
        if (t + 1 < NTILE) {
            const uint32_t nstb = smb + ((t + 1) % 3) * STG_SZ;
            const __half* ks = g_k16 + gb + (size_t)(kv_beg + (t + 1) * 64 + srow) * HEAD + sc * 8;
            const __half* vs = g_v16 + gb + (size_t)(kv_beg + (t + 1) * 64 + srow) * HEAD + sc * 8;
            cp16(nstb + dOff, ks); cp16(nstb + dOff + 16, ks + 8);
            cp16(nstb + 9216 + dOff, vs); cp16(nstb + 9216 + dOff + 16, vs + 8);
            asm volatile("cp.async.commit_group;");
            asm volatile("cp.async.wait_group 1;");
        } else {
            asm volatile("cp.async.wait_group 0;");
        }
        __syncthreads();

        const uint32_t aK = stb + kOff;
        float S[8][4];
#pragma unroll
        for (int nb = 0; nb < 8; nb++)
#pragma unroll
            for (int j = 0; j < 4; j++) S[nb][j] = 0.f;
#pragma unroll
        for (int ks = 0; ks < 4; ks++)
#pragma unroll
            for (int p = 0; p < 4; p++) {
                uint32_t bb[4];
                ldsm_x4(bb, aK + p * 2304 + ks * 32);
                mma_f16(S[2 * p    ], Aq[ks], bb[0], bb[1]);
                mma_f16(S[2 * p + 1], Aq[ks], bb[2], bb[3]);
            }

        float mt0 = -1e30f, mt1 = -1e30f;
#pragma unroll
        for (int nb = 0; nb < 8; nb++) {
            mt0 = fmaxf(mt0, fmaxf(S[nb][0], S[nb][1]));
            mt1 = fmaxf(mt1, fmaxf(S[nb][2], S[nb][3]));
        }
        mt0 = fmaxf(mt0, __shfl_xor_sync(0xffffffffu, mt0, 1));
        mt0 = fmaxf(mt0, __shfl_xor_sync(0xffffffffu, mt0, 2));
        mt1 = fmaxf(mt1, __shfl_xor_sync(0xffffffffu, mt1, 1));
        mt1 = fmaxf(mt1, __shfl_xor_sync(0xffffffffu, mt1, 2));

        float mn0 = fmaxf(mrow0, mt0);
        float mn1 = fmaxf(mrow1, mt1);
        float corr0 = exp2a(mrow0 - mn0);
        float corr1 = exp2a(mrow1 - mn1);

        float rs0 = 0.f, rs1 = 0.f;
#pragma unroll
        for (int nb = 0; nb < 8; nb++) {
            S[nb][0] = exp2a(S[nb][0] - mn0);
            S[nb][1] = exp2a(S[nb][1] - mn0);
            S[nb][2] = exp2a(S[nb][2] - mn1);
            S[nb][3] = exp2a(S[nb][3] - mn1);
            rs0 += S[nb][0] + S[nb][1];
            rs1 += S[nb][2] + S[nb][3];
        }
        rs0 += __shfl_xor_sync(0xffffffffu, rs0, 1);
        rs0 += __shfl_xor_sync(0xffffffffu, rs0, 2);
        rs1 += __shfl_xor_sync(0xffffffffu, rs1, 1);
        rs1 += __shfl_xor_sync(0xffffffffu, rs1, 2);

        lrow0 = lrow0 * corr0 + rs0;
        lrow1 = lrow1 * corr1 + rs1;
        mrow0 = mn0;
        mrow1 = mn1;

#pragma unroll
        for (int nb = 0; nb < 8; nb++) {
            O[nb][0] *= corr0;
            O[nb][1] *= corr0;
            O[nb][2] *= corr1;
            O[nb][3] *= corr1;
        }

        const uint32_t aV = stb + vOff;
#pragma unroll
        for (int ks = 0; ks < 4; ks++) {
            uint32_t pa[4];
            pa[0] = packh2(S[2 * ks    ][0], S[2 * ks    ][1]);
            pa[1] = packh2(S[2 * ks    ][2], S[2 * ks    ][3]);
            pa[2] = packh2(S[2 * ks + 1][0], S[2 * ks + 1][1]);
            pa[3] = packh2(S[2 * ks + 1][2], S[2 * ks + 1][3]);
#pragma unroll
            for (int p = 0; p < 4; p++) {
                uint32_t bb[4];
                ldsm_x4t(bb, aV + ks * 2304 + p * 32);
                mma_f16(O[2 * p    ], pa, bb[0], bb[1]);
                mma_f16(O[2 * p + 1], pa, bb[2], bb[3]);
            }
        }
    }

    int r0g = b * SEQ + q0 + w * 16 + ly;
#pragma unroll
    for (int nb = 0; nb < 8; nb++) {
        *reinterpret_cast<float2*>(&g_po[z][(size_t)r0g * HEAD + nb * 8 + 2 * lx]) =
            make_float2(O[nb][0], O[nb][1]);
        *reinterpret_cast<float2*>(&g_po[z][(size_t)(r0g + 8) * HEAD + nb * 8 + 2 * lx]) =
            make_float2(O[nb][2], O[nb][3]);
    }
    if (lx == 0) {
        g_pm[z][r0g] = mrow0;      g_pl[z][r0g] = lrow0;
        g_pm[z][r0g + 8] = mrow1;  g_pl[z][r0g + 8] = lrow1;
    }
}

// ---------------------------------------------------------------------------
// Kernel 3: output projection, fp16 mma, fused split-KV combine.
// B (W_out fp16) staged by cp.async (issued before combine math, overlapped),
// fragments via ldsm trans at stride 272 (conflict-free).
// ---------------------------------------------------------------------------
#define OBM 128
#define OBN 128

__global__ __launch_bounds__(256, 2) void out_fp16(const float* __restrict__ bout,
                                                   float* __restrict__ out) {
    __shared__ __half sA[128 * 72];     // [m][k] 18432 B
    __shared__ __half sB[64 * 136];     // [k][n] rows of 272 B -> 17408 B

    const int bm = blockIdx.x * OBM;
    const int bn = blockIdx.y * OBN;
    const int tid = threadIdx.x;
    const int w = tid >> 5;
    const int lane = tid & 31;
    const int ly = lane >> 2;
    const int lx = lane & 3;

    const uint32_t bA = (uint32_t)__cvta_generic_to_shared(sA);
    const uint32_t bB = (uint32_t)__cvta_generic_to_shared(sB);

    // B: cp.async W_out tile [64 k][128 n] (issued first; overlaps combine)
    {
        const int row = tid >> 2;            // 0..63
        const int col = (tid & 3);           // x4 iters covers 16 chunks
#pragma unroll
        for (int i = 0; i < 4; i++) {
            int c = col + i * 4;
            cp16(bB + row * 272 + c * 16,
                 g_wo16 + (size_t)row * EMB + bn + c * 8);
        }
        asm volatile("cp.async.commit_group;");
    }

    // A: combine partial O halves -> fp16
#pragma unroll
    for (int i = 0; i < 8; i++) {
        int f4 = tid + i * 256;
        int row = f4 >> 4;
        int c4 = f4 & 15;
        int rg = bm + row;
        float m0 = g_pm[0][rg], m1 = g_pm[1][rg];
        float mx = fmaxf(m0, m1);
        float w0 = exp2a(m0 - mx), w1 = exp2a(m1 - mx);
        float inv = 1.f / (w0 * g_pl[0][rg] + w1 * g_pl[1][rg]);
        float4 a = *reinterpret_cast<const float4*>(&g_po[0][(size_t)rg * HEAD + c4 * 4]);
        float4 c = *reinterpret_cast<const float4*>(&g_po[1][(size_t)rg * HEAD + c4 * 4]);
        uint2 pk = make_uint2(
            packh2((w0 * a.x + w1 * c.x) * inv, (w0 * a.y + w1 * c.y) * inv),
            packh2((w0 * a.z + w1 * c.z) * inv, (w0 * a.w + w1 * c.w) * inv));
        *reinterpret_cast<uint2*>(&sA[row * 72 + c4 * 4]) = pk;
    }
    asm volatile("cp.async.wait_group 0;");
    __syncthreads();

    const int ar = (lane & 7) + ((lane >> 3) & 1) * 8;
    const uint32_t aA = bA + (w * 16 + ar) * 144 + (lane >> 4) * 16;
    const uint32_t aB = bB + (lane & 15) * 272 + (lane >> 4) * 16;

    uint32_t Aa[4][4];
#pragma unroll
    for (int ks = 0; ks < 4; ks++) ldsm_x4(Aa[ks], aA + ks * 32);

    float acc[16][4] = {};
#pragma unroll
    for (int ks = 0; ks < 4; ks++) {
#pragma unroll
        for (int p = 0; p < 8; p++) {
            uint32_t bb[4];
            ldsm_x4t(bb, aB + ks * 4352 + p * 32);   // 4352 = 16*272
            mma_f16(acc[2 * p    ], Aa[ks], bb[0], bb[1]);
            mma_f16(acc[2 * p + 1], Aa[ks], bb[2], bb[3]);
        }
    }

    int r0 = bm + w * 16 + ly;
#pragma unroll
    for (int nb = 0; nb < 16; nb++) {
        int col = bn + nb * 8 + 2 * lx;
        float b0 = bout[col], b1 = bout[col + 1];
        *reinterpret_cast<float2*>(&out[(size_t)r0 * EMB + col]) =
            make_float2(acc[nb][0] + b0, acc[nb][1] + b1);
        *reinterpret_cast<float2*>(&out[(size_t)(r0 + 8) * EMB + col]) =
            make_float2(acc[nb][2] + b0, acc[nb][3] + b1);
    }
}

// ---------------------------------------------------------------------------
extern "C" void kernel_launch(void* const* d_in, const int* in_sizes, int n_in,
                              void* d_out, int out_size) {
    const float* x     = (const float*)d_in[0];
    const float* W_qkv = (const float*)d_in[1];
    const float* b_qkv = (const float*)d_in[2];
    const float* W_out = (const float*)d_in[3];
    const float* b_out = (const float*)d_in[4];
    float* out = (float*)d_out;

    conv16<<<CONV_BLOCKS, 256>>>(x, W_qkv, W_out);

    cudaFuncSetAttribute(qkv_fp16, cudaFuncAttributeMaxDynamicSharedMemorySize, QKV_SMEM);
    qkv_fp16<<<dim3(3, MTOT / 128), 256, QKV_SMEM>>>(b_qkv);

    cudaFuncSetAttribute(attn_fp16, cudaFuncAttributeMaxDynamicSharedMemorySize, ATT_SMEM);
    attn_fp16<<<dim3(SEQ / BQ, BATCH, 2), 256, ATT_SMEM>>>();

    out_fp16<<<dim3(MTOT / OBM, EMB / OBN), 256>>>(b_out, out);
}

// round 14
// speedup vs baseline: 1.0648x; 1.0648x over previous
#include <cuda_runtime.h>
#include <cuda_fp16.h>
#include <cstdint>

#define BATCH 4
#define SEQ   4096
#define EMB   1024
#define HEAD  64
#define H3    192
#define MTOT  (BATCH*SEQ)   // 16384

// Scratch (allocation-free rule: device globals)
__device__ __align__(16) __half g_x16[MTOT * EMB];    // 33.5 MB fp16 x
__device__ __align__(16) __half g_wq16[EMB * H3];
__device__ __align__(16) __half g_wo16[HEAD * EMB];
__device__ __align__(16) __half g_q16[MTOT * HEAD];   // q pre-scaled
__device__ __align__(16) __half g_k16[MTOT * HEAD];
__device__ __align__(16) __half g_v16[MTOT * HEAD];
__device__ __align__(16) float  g_po[2][MTOT * HEAD]; // partial O (unnormalized)
__device__ __align__(16) float  g_pm[2][MTOT];
__device__ __align__(16) float  g_pl[2][MTOT];

// ---------------------------------------------------------------------------
// Helpers
// ---------------------------------------------------------------------------
__device__ __forceinline__ float exp2a(float x) {
    float y;
    asm("ex2.approx.f32 %0, %1;" : "=f"(y) : "f"(x));
    return y;
}
__device__ __forceinline__ uint32_t exp2h2(uint32_t x) {
    uint32_t y;
    asm("ex2.approx.f16x2 %0, %1;" : "=r"(y) : "r"(x));
    return y;
}
__device__ __forceinline__ void mma_f16(float c[4], const uint32_t a[4],
                                        uint32_t b0, uint32_t b1) {
    asm volatile(
        "mma.sync.aligned.m16n8k16.row.col.f32.f16.f16.f32 "
        "{%0,%1,%2,%3}, {%4,%5,%6,%7}, {%8,%9}, {%0,%1,%2,%3};\n"
        : "+f"(c[0]), "+f"(c[1]), "+f"(c[2]), "+f"(c[3])
        : "r"(a[0]), "r"(a[1]), "r"(a[2]), "r"(a[3]), "r"(b0), "r"(b1));
}
__device__ __forceinline__ void ldsm_x4(uint32_t r[4], uint32_t addr) {
    asm volatile("ldmatrix.sync.aligned.m8n8.x4.shared.b16 {%0,%1,%2,%3}, [%4];"
                 : "=r"(r[0]), "=r"(r[1]), "=r"(r[2]), "=r"(r[3]) : "r"(addr));
}
__device__ __forceinline__ void ldsm_x4t(uint32_t r[4], uint32_t addr) {
    asm volatile("ldmatrix.sync.aligned.m8n8.x4.trans.shared.b16 {%0,%1,%2,%3}, [%4];"
                 : "=r"(r[0]), "=r"(r[1]), "=r"(r[2]), "=r"(r[3]) : "r"(addr));
}
__device__ __forceinline__ void cp16(uint32_t dst, const void* src) {
    asm volatile("cp.async.cg.shared.global [%0], [%1], 16;" :: "r"(dst), "l"(src));
}
__device__ __forceinline__ uint32_t packh2(float x, float y) {
    __half2 h = __floats2half2_rn(x, y);
    return *reinterpret_cast<uint32_t*>(&h);
}

#define QSCALE (0.125f * 1.44269504088896340736f)   // (1/sqrt(64)) * log2(e)

// ---------------------------------------------------------------------------
// Kernel 0: fp32 -> fp16 prepass for x, W_qkv, W_out.
// ---------------------------------------------------------------------------
#define NX  (MTOT * EMB)    // 16777216
#define NWQ (EMB * H3)      // 196608
#define NWO (HEAD * EMB)    // 65536
#define CONV_BLOCKS ((NX + NWQ + NWO) / (8 * 256))   // 8320

__global__ __launch_bounds__(256) void conv16(const float* __restrict__ x,
                                              const float* __restrict__ Wq,
                                              const float* __restrict__ Wo) {
    size_t i = ((size_t)blockIdx.x * 256 + threadIdx.x) * 8;
    const float* src;
    __half* dst;
    size_t off;
    if (i < NX)            { src = x;  dst = g_x16;  off = i; }
    else if (i < NX + NWQ) { src = Wq; dst = g_wq16; off = i - NX; }
    else                   { src = Wo; dst = g_wo16; off = i - NX - NWQ; }
    float4 a = *reinterpret_cast<const float4*>(src + off);
    float4 b = *reinterpret_cast<const float4*>(src + off + 4);
    uint4 o = make_uint4(packh2(a.x, a.y), packh2(a.z, a.w),
                         packh2(b.x, b.y), packh2(b.z, b.w));
    *reinterpret_cast<uint4*>(dst + off) = o;
}

// ---------------------------------------------------------------------------
// Kernel 1: QKV projection, pure fp16 GEMM, 3-stage cp.async ring. Grid
// (3, M/128): the 3 output types share each x tile through L2. Unchanged.
// ---------------------------------------------------------------------------
#define QSTG 27648
#define QKV_SMEM (3 * QSTG)

__global__ __launch_bounds__(256, 2) void qkv_fp16(const float* __restrict__ bias) {
    extern __shared__ __half qsm[];

    const int bn = blockIdx.x * 64;
    const int bm = blockIdx.y * 128;
    const int tid = threadIdx.x;
    const int w = tid >> 5;
    const int lane = tid & 31;
    const int ly = lane >> 2;
    const int lx = lane & 3;

    const uint32_t smb = (uint32_t)__cvta_generic_to_shared(qsm);

    const int ar = (lane & 7) + ((lane >> 3) & 1) * 8;
    const uint32_t offA = (w * 16 + ar) * 144 + (lane >> 4) * 16;
    const uint32_t offB = 18432 + (lane & 15) * 144 + (lane >> 4) * 16;

    const int arow = tid >> 3, acol = tid & 7;
    const int brow = tid >> 3, bcol = tid & 7;

    auto load_tile = [&](int t) {
        const uint32_t sb = smb + (t % 3) * QSTG;
#pragma unroll
        for (int i = 0; i < 4; i++) {
            int row = arow + i * 32;
            cp16(sb + row * 144 + acol * 16,
                 g_x16 + (size_t)(bm + row) * EMB + t * 64 + acol * 8);
        }
#pragma unroll
        for (int i = 0; i < 2; i++) {
            int row = brow + i * 32;
            cp16(sb + 18432 + row * 144 + bcol * 16,
                 g_wq16 + (size_t)(t * 64 + row) * H3 + bn + bcol * 8);
        }
        asm volatile("cp.async.commit_group;");
    };

    load_tile(0);

    float acc[8][4] = {};

    for (int t = 0; t < 16; t++) {
        if (t + 1 < 16) {
            load_tile(t + 1);
            asm volatile("cp.async.wait_group 1;");
        } else {
            asm volatile("cp.async.wait_group 0;");
        }
        __syncthreads();

        const uint32_t sb = smb + (t % 3) * QSTG;
        uint32_t Aa[4][4];
#pragma unroll
        for (int ks = 0; ks < 4; ks++) ldsm_x4(Aa[ks], sb + offA + ks * 32);

#pragma unroll
        for (int ks = 0; ks < 4; ks++) {
#pragma unroll
            for (int p = 0; p < 4; p++) {
                uint32_t bb[4];
                ldsm_x4t(bb, sb + offB + ks * 2304 + p * 32);
                mma_f16(acc[2 * p    ], Aa[ks], bb[0], bb[1]);
                mma_f16(acc[2 * p + 1], Aa[ks], bb[2], bb[3]);
            }
        }
    }

    __half* dst = (blockIdx.x == 0) ? g_q16 : (blockIdx.x == 1) ? g_k16 : g_v16;
    const float sc = (blockIdx.x == 0) ? QSCALE : 1.0f;
    int r0 = bm + w * 16 + ly;
#pragma unroll
    for (int nb = 0; nb < 8; nb++) {
        int col = nb * 8 + 2 * lx;
        float b0 = bias[bn + col], b1 = bias[bn + col + 1];
        __half2 h0 = __floats2half2_rn((acc[nb][0] + b0) * sc, (acc[nb][1] + b1) * sc);
        __half2 h1 = __floats2half2_rn((acc[nb][2] + b0) * sc, (acc[nb][3] + b1) * sc);
        *reinterpret_cast<__half2*>(&dst[(size_t)r0 * HEAD + col]) = h0;
        *reinterpret_cast<__half2*>(&dst[(size_t)(r0 + 8) * HEAD + col]) = h1;
    }
}

// ---------------------------------------------------------------------------
// Kernel 2: fp16 flash attention. 3-stage cp.async ring, register-resident P,
// split-KV (z). NEW: ex2.approx.f16x2 softmax (output is the packed P frag),
// HADD2-tree row sums.
// ---------------------------------------------------------------------------
#define BQ     128
#define KVHALF (SEQ / 2)
#define NTILE  (KVHALF / 64)
#define STG_SZ (2 * 64 * 144)
#define ATT_SMEM (3 * STG_SZ + 128 * 144)

__global__ __launch_bounds__(256, 2) void attn_fp16() {
    extern __shared__ __half smh[];

    const int b    = blockIdx.y;
    const int q0   = blockIdx.x * BQ;
    const int z    = blockIdx.z;
    const int tid  = threadIdx.x;
    const int w    = tid >> 5;
    const int lane = tid & 31;
    const int ly   = lane >> 2;
    const int lx   = lane & 3;

    const uint32_t smb = (uint32_t)__cvta_generic_to_shared(smh);
    const uint32_t bQ  = smb + 3 * STG_SZ;

    const int srow = tid >> 2;
    const int sc   = (tid & 3) * 2;
    const uint32_t dOff = srow * 144 + sc * 16;
    const size_t gb = (size_t)b * SEQ * HEAD;
    const int kv_beg = z * KVHALF;

    {
        const __half* ks = g_k16 + gb + (size_t)(kv_beg + srow) * HEAD + sc * 8;
        const __half* vs = g_v16 + gb + (size_t)(kv_beg + srow) * HEAD + sc * 8;
        cp16(smb + dOff, ks); cp16(smb + dOff + 16, ks + 8);
        cp16(smb + 9216 + dOff, vs); cp16(smb + 9216 + dOff + 16, vs + 8);
        asm volatile("cp.async.commit_group;");
    }

#pragma unroll
    for (int i = 0; i < 4; i++) {
        int idx = tid + i * 256;
        int row = idx >> 3, c = idx & 7;
        uint4 v = *reinterpret_cast<const uint4*>(
            g_q16 + gb + (size_t)(q0 + row) * HEAD + c * 8);
        *reinterpret_cast<uint4*>(
            reinterpret_cast<char*>(smh) + 3 * STG_SZ + row * 144 + c * 16) = v;
    }
    __syncthreads();

    uint32_t Aq[4][4];
    {
        const int qr = (lane & 7) + ((lane >> 3) & 1) * 8;
        uint32_t aQ = bQ + (w * 16 + qr) * 144 + (lane >> 4) * 16;
#pragma unroll
        for (int ks = 0; ks < 4; ks++) ldsm_x4(Aq[ks], aQ + ks * 32);
    }

    float O[8][4];
    float mrow0 = -1e30f, mrow1 = -1e30f, lrow0 = 0.f, lrow1 = 0.f;
#pragma unroll
    for (int nb = 0; nb < 8; nb++)
#pragma unroll
        for (int j = 0; j < 4; j++) O[nb][j] = 0.f;

    const uint32_t kOff = (((lane >> 4) & 1) * 8 + (lane & 7)) * 144 + ((lane >> 3) & 1) * 16;
    const uint32_t vOff = 9216 + (lane & 15) * 144 + (lane >> 4) * 16;

    for (int t = 0; t < NTILE; t++) {
        const uint32_t stb = smb + (t % 3) * STG_SZ;
        if (t + 1 < NTILE) {
            const uint32_t nstb = smb + ((t + 1) % 3) * STG_SZ;
            const __half* ks = g_k16 + gb + (size_t)(kv_beg + (t + 1) * 64 + srow) * HEAD + sc * 8;
            const __half* vs = g_v16 + gb + (size_t)(kv_beg + (t + 1) * 64 + srow) * HEAD + sc * 8;
            cp16(nstb + dOff, ks); cp16(nstb + dOff + 16, ks + 8);
            cp16(nstb + 9216 + dOff, vs); cp16(nstb + 9216 + dOff + 16, vs + 8);
            asm volatile("cp.async.commit_group;");
            asm volatile("cp.async.wait_group 1;");
        } else {
            asm volatile("cp.async.wait_group 0;");
        }
        __syncthreads();

        // --- S = Q K^T ---
        const uint32_t aK = stb + kOff;
        float S[8][4];
#pragma unroll
        for (int nb = 0; nb < 8; nb++)
#pragma unroll
            for (int j = 0; j < 4; j++) S[nb][j] = 0.f;
#pragma unroll
        for (int ks = 0; ks < 4; ks++)
#pragma unroll
            for (int p = 0; p < 4; p++) {
                uint32_t bb[4];
                ldsm_x4(bb, aK + p * 2304 + ks * 32);
                mma_f16(S[2 * p    ], Aq[ks], bb[0], bb[1]);
                mma_f16(S[2 * p + 1], Aq[ks], bb[2], bb[3]);
            }

        // --- online softmax: row max ---
        float mt0 = -1e30f, mt1 = -1e30f;
#pragma unroll
        for (int nb = 0; nb < 8; nb++) {
            mt0 = fmaxf(mt0, fmaxf(S[nb][0], S[nb][1]));
            mt1 = fmaxf(mt1, fmaxf(S[nb][2], S[nb][3]));
        }
        mt0 = fmaxf(mt0, __shfl_xor_sync(0xffffffffu, mt0, 1));
        mt0 = fmaxf(mt0, __shfl_xor_sync(0xffffffffu, mt0, 2));
        mt1 = fmaxf(mt1, __shfl_xor_sync(0xffffffffu, mt1, 1));
        mt1 = fmaxf(mt1, __shfl_xor_sync(0xffffffffu, mt1, 2));

        float mn0 = fmaxf(mrow0, mt0);
        float mn1 = fmaxf(mrow1, mt1);
        float corr0 = exp2a(mrow0 - mn0);
        float corr1 = exp2a(mrow1 - mn1);

        // --- exp in f16x2: result IS the packed P fragment ---
        uint32_t Ph[8][2];
#pragma unroll
        for (int nb = 0; nb < 8; nb++) {
            Ph[nb][0] = exp2h2(packh2(S[nb][0] - mn0, S[nb][1] - mn0));
            Ph[nb][1] = exp2h2(packh2(S[nb][2] - mn1, S[nb][3] - mn1));
        }
        // --- row sums via HADD2 tree, one upconvert per row ---
        float rs0, rs1;
        {
            __half2 a0 = __hadd2(*(__half2*)&Ph[0][0], *(__half2*)&Ph[4][0]);
            __half2 a1 = __hadd2(*(__half2*)&Ph[1][0], *(__half2*)&Ph[5][0]);
            __half2 a2 = __hadd2(*(__half2*)&Ph[2][0], *(__half2*)&Ph[6][0]);
            __half2 a3 = __hadd2(*(__half2*)&Ph[3][0], *(__half2*)&Ph[7][0]);
            __half2 s = __hadd2(__hadd2(a0, a1), __hadd2(a2, a3));
            float2 f = __half22float2(s);
            rs0 = f.x + f.y;
            __half2 b0 = __hadd2(*(__half2*)&Ph[0][1], *(__half2*)&Ph[4][1]);
            __half2 b1 = __hadd2(*(__half2*)&Ph[1][1], *(__half2*)&Ph[5][1]);
            __half2 b2 = __hadd2(*(__half2*)&Ph[2][1], *(__half2*)&Ph[6][1]);
            __half2 b3 = __hadd2(*(__half2*)&Ph[3][1], *(__half2*)&Ph[7][1]);
            __half2 u = __hadd2(__hadd2(b0, b1), __hadd2(b2, b3));
            float2 g = __half22float2(u);
            rs1 = g.x + g.y;
        }
        rs0 += __shfl_xor_sync(0xffffffffu, rs0, 1);
        rs0 += __shfl_xor_sync(0xffffffffu, rs0, 2);
        rs1 += __shfl_xor_sync(0xffffffffu, rs1, 1);
        rs1 += __shfl_xor_sync(0xffffffffu, rs1, 2);

        lrow0 = lrow0 * corr0 + rs0;
        lrow1 = lrow1 * corr1 + rs1;
        mrow0 = mn0;
        mrow1 = mn1;

#pragma unroll
        for (int nb = 0; nb < 8; nb++) {
            O[nb][0] *= corr0;
            O[nb][1] *= corr0;
            O[nb][2] *= corr1;
            O[nb][3] *= corr1;
        }

        // --- O += P V : P fragments straight from Ph ---
        const uint32_t aV = stb + vOff;
#pragma unroll
        for (int ks = 0; ks < 4; ks++) {
            uint32_t pa[4];
            pa[0] = Ph[2 * ks    ][0];
            pa[1] = Ph[2 * ks    ][1];
            pa[2] = Ph[2 * ks + 1][0];
            pa[3] = Ph[2 * ks + 1][1];
#pragma unroll
            for (int p = 0; p < 4; p++) {
                uint32_t bb[4];
                ldsm_x4t(bb, aV + ks * 2304 + p * 32);
                mma_f16(O[2 * p    ], pa, bb[0], bb[1]);
                mma_f16(O[2 * p + 1], pa, bb[2], bb[3]);
            }
        }
    }

    int r0g = b * SEQ + q0 + w * 16 + ly;
#pragma unroll
    for (int nb = 0; nb < 8; nb++) {
        *reinterpret_cast<float2*>(&g_po[z][(size_t)r0g * HEAD + nb * 8 + 2 * lx]) =
            make_float2(O[nb][0], O[nb][1]);
        *reinterpret_cast<float2*>(&g_po[z][(size_t)(r0g + 8) * HEAD + nb * 8 + 2 * lx]) =
            make_float2(O[nb][2], O[nb][3]);
    }
    if (lx == 0) {
        g_pm[z][r0g] = mrow0;      g_pl[z][r0g] = lrow0;
        g_pm[z][r0g + 8] = mrow1;  g_pl[z][r0g + 8] = lrow1;
    }
}

// ---------------------------------------------------------------------------
// Kernel 3: output projection, restructured. Block = 128 rows x 256 cols as
// 4 x 64-wide subtiles; A combined ONCE per block, A-frags register-resident;
// W_out subtiles streamed through a 3-buffer cp.async ring.
// ---------------------------------------------------------------------------
__global__ __launch_bounds__(256, 2) void out_fp16(const float* __restrict__ bout,
                                                   float* __restrict__ out) {
    __shared__ __half osm[(18432 + 3 * 9216) / 2];   // A 128x72 + 3 B bufs 64x72

    const int bm = blockIdx.x * 128;
    const int n0 = blockIdx.y * 256;
    const int tid = threadIdx.x;
    const int w = tid >> 5;
    const int lane = tid & 31;
    const int ly = lane >> 2;
    const int lx = lane & 3;

    __half* sA = osm;
    const uint32_t bA = (uint32_t)__cvta_generic_to_shared(osm);
    const uint32_t bB = bA + 18432;

    // B subtile loader: [64 k][64 n] fp16, rows 144 B
    const int brow = tid >> 2;
    const int bcol = (tid & 3) * 2;
    auto loadB = [&](int j) {
        uint32_t sb = bB + (j % 3) * 9216;
        cp16(sb + brow * 144 + bcol * 16,
             g_wo16 + (size_t)brow * EMB + n0 + j * 64 + bcol * 8);
        cp16(sb + brow * 144 + (bcol + 1) * 16,
             g_wo16 + (size_t)brow * EMB + n0 + j * 64 + (bcol + 1) * 8);
        asm volatile("cp.async.commit_group;");
    };

    loadB(0);
    loadB(1);

    // A: combine partial O halves -> fp16 (once per block)
#pragma unroll
    for (int i = 0; i < 8; i++) {
        int f4 = tid + i * 256;
        int row = f4 >> 4;
        int c4 = f4 & 15;
        int rg = bm + row;
        float m0 = g_pm[0][rg], m1 = g_pm[1][rg];
        float mx = fmaxf(m0, m1);
        float w0 = exp2a(m0 - mx), w1 = exp2a(m1 - mx);
        float inv = 1.f / (w0 * g_pl[0][rg] + w1 * g_pl[1][rg]);
        float4 a = *reinterpret_cast<const float4*>(&g_po[0][(size_t)rg * HEAD + c4 * 4]);
        float4 c = *reinterpret_cast<const float4*>(&g_po[1][(size_t)rg * HEAD + c4 * 4]);
        uint2 pk = make_uint2(
            packh2((w0 * a.x + w1 * c.x) * inv, (w0 * a.y + w1 * c.y) * inv),
            packh2((w0 * a.z + w1 * c.z) * inv, (w0 * a.w + w1 * c.w) * inv));
        *reinterpret_cast<uint2*>(&sA[row * 72 + c4 * 4]) = pk;
    }

    const int ar = (lane & 7) + ((lane >> 3) & 1) * 8;
    const uint32_t aA = bA + (w * 16 + ar) * 144 + (lane >> 4) * 16;
    const uint32_t offB = (lane & 15) * 144 + (lane >> 4) * 16;

    uint32_t Aa[4][4];
    int r0 = bm + w * 16 + ly;

    for (int j = 0; j < 4; j++) {
        asm volatile("cp.async.wait_group 1;");
        __syncthreads();
        if (j == 0) {
#pragma unroll
            for (int ks = 0; ks < 4; ks++) ldsm_x4(Aa[ks], aA + ks * 32);
        }
        if (j + 2 < 4) loadB(j + 2);

        const uint32_t sb = bB + (j % 3) * 9216;
        float acc[8][4] = {};
#pragma unroll
        for (int ks = 0; ks < 4; ks++) {
#pragma unroll
            for (int p = 0; p < 4; p++) {
                uint32_t bb[4];
                ldsm_x4t(bb, sb + offB + ks * 2304 + p * 32);
                mma_f16(acc[2 * p    ], Aa[ks], bb[0], bb[1]);
                mma_f16(acc[2 * p + 1], Aa[ks], bb[2], bb[3]);
            }
        }
        __syncthreads();   // all warps done reading buffer j before it is reused

#pragma unroll
        for (int nb = 0; nb < 8; nb++) {
            int col = n0 + j * 64 + nb * 8 + 2 * lx;
            float b0 = bout[col], b1 = bout[col + 1];
            *reinterpret_cast<float2*>(&out[(size_t)r0 * EMB + col]) =
                make_float2(acc[nb][0] + b0, acc[nb][1] + b1);
            *reinterpret_cast<float2*>(&out[(size_t)(r0 + 8) * EMB + col]) =
                make_float2(acc[nb][2] + b0, acc[nb][3] + b1);
        }
    }
}

// ---------------------------------------------------------------------------
extern "C" void kernel_launch(void* const* d_in, const int* in_sizes, int n_in,
                              void* d_out, int out_size) {
    const float* x     = (const float*)d_in[0];
    const float* W_qkv = (const float*)d_in[1];
    const float* b_qkv = (const float*)d_in[2];
    const float* W_out = (const float*)d_in[3];
    const float* b_out = (const float*)d_in[4];
    float* out = (float*)d_out;

    conv16<<<CONV_BLOCKS, 256>>>(x, W_qkv, W_out);

    cudaFuncSetAttribute(qkv_fp16, cudaFuncAttributeMaxDynamicSharedMemorySize, QKV_SMEM);
    qkv_fp16<<<dim3(3, MTOT / 128), 256, QKV_SMEM>>>(b_qkv);

    cudaFuncSetAttribute(attn_fp16, cudaFuncAttributeMaxDynamicSharedMemorySize, ATT_SMEM);
    attn_fp16<<<dim3(SEQ / BQ, BATCH, 2), 256, ATT_SMEM>>>();

    out_fp16<<<dim3(MTOT / 128, EMB / 256), 256>>>(b_out, out);
}